// round 16
// baseline (speedup 1.0000x reference)
#include <cuda_runtime.h>

#define Bv 16
#define Cv 512
#define Nv 9216
#define Kv 32
#define TN 512
#define NT (Nv / TN)      // 18 n-tiles for k_assign

#define CC 16             // k_assign: c per staged chunk
#define NCC (Cv / CC)     // 32 chunks
#define XPA 520           // k_assign x tile pitch (words) — conflict-free B-frag reads
#define CWP 20            // cw tile pitch (words) — conflict-free A-frag reads

#define SL 8              // k_agg n-slices per (b, c-half)
#define NSL (Nv / SL)     // 1152 n per slice
#define CHN 16            // k_agg n per staged chunk
#define NCH (NSL / CHN)   // 72 chunks
#define CHC 256           // k_agg c per block (c-half)
#define RP 20             // raw fp32 x pitch (words)
#define TP 12             // bf16x2 tile pitch (words)

// scratch (no cudaMalloc allowed)
__device__ __align__(16) unsigned g_aw2h[(size_t)Bv * Kv * (Nv / 2)]; // 9.4 MB bf16x2 hi
__device__ __align__(16) unsigned g_aw2l[(size_t)Bv * Kv * (Nv / 2)]; // 9.4 MB bf16x2 lo
__device__ float g_sawp[Bv * NT * Kv];                                // per-tile sums of aw
__device__ __align__(16) float g_part[(size_t)SL * Bv * Kv * Cv];     // 8.4 MB partials

typedef unsigned long long u64;

__device__ __forceinline__ u64 pack2(float lo, float hi) {
    u64 r; asm("mov.b64 %0,{%1,%2};" : "=l"(r) : "f"(lo), "f"(hi)); return r;
}
__device__ __forceinline__ void unpack2(u64 v, float& lo, float& hi) {
    asm("mov.b64 {%0,%1},%2;" : "=f"(lo), "=f"(hi) : "l"(v));
}
__device__ __forceinline__ u64 ffma2(u64 a, u64 b, u64 c) {
    u64 d; asm("fma.rn.f32x2 %0,%1,%2,%3;" : "=l"(d) : "l"(a), "l"(b), "l"(c)); return d;
}
__device__ __forceinline__ unsigned smem_u32(const void* p) {
    unsigned r;
    asm("{ .reg .u64 t; cvta.to.shared.u64 t, %1; cvt.u32.u64 %0, t; }" : "=r"(r) : "l"(p));
    return r;
}
__device__ __forceinline__ void cp16(unsigned dst, const void* src) {
    asm volatile("cp.async.ca.shared.global [%0], [%1], 16;" :: "r"(dst), "l"(src));
}
#define CP_COMMIT() asm volatile("cp.async.commit_group;" ::: "memory")
#define CP_WAIT(N)  asm volatile("cp.async.wait_group %0;" :: "n"(N) : "memory")

// bf16x2 pack: result.lo = bf16(lo), result.hi = bf16(hi)
__device__ __forceinline__ unsigned bf2(float hi, float lo) {
    unsigned u; asm("cvt.rn.bf16x2.f32 %0, %1, %2;" : "=r"(u) : "f"(hi), "f"(lo)); return u;
}
__device__ __forceinline__ float blo(unsigned u) { return __uint_as_float(u << 16); }
__device__ __forceinline__ float bhi(unsigned u) { return __uint_as_float(u & 0xFFFF0000u); }

// tf32 round (valid f32 bit pattern)
__device__ __forceinline__ unsigned tf32_of(float x) {
    unsigned u; asm("cvt.rna.tf32.f32 %0, %1;" : "=r"(u) : "f"(x)); return u;
}

// m16n8k8 tf32 mma: D += A*B (A row-major, B col-major), fp32 accumulate
#define MMA8(d, a0, a1, a2, a3, b0, b1) \
    asm volatile("mma.sync.aligned.m16n8k8.row.col.f32.tf32.tf32.f32 " \
        "{%0,%1,%2,%3}, {%4,%5,%6,%7}, {%8,%9}, {%0,%1,%2,%3};" \
        : "+f"(d[0]), "+f"(d[1]), "+f"(d[2]), "+f"(d[3]) \
        : "r"(a0), "r"(a1), "r"(a2), "r"(a3), "r"(b0), "r"(b1))

// m16n8k16 bf16 mma: D += A*B, fp32 accumulate
#define MMA16(d, a0, a1, a2, a3, b0, b1) \
    asm volatile("mma.sync.aligned.m16n8k16.row.col.f32.bf16.bf16.f32 " \
        "{%0,%1,%2,%3}, {%4,%5,%6,%7}, {%8,%9}, {%0,%1,%2,%3};" \
        : "+f"(d[0]), "+f"(d[1]), "+f"(d[2]), "+f"(d[3]) \
        : "r"(a0), "r"(a1), "r"(a2), "r"(a3), "r"(b0), "r"(b1))

// ---------------------------------------------------------------------------
// Kernel 1 (REBUILT, tensor cores): xc = x . cw^T via mma m16n8k8 tf32,
// 3-pass hi/lo split. A = cw[k][c] (row-major: direct), B = x[c][n]
// ((C,N) storage IS col-major k8 x n8: ZERO transpose). x2 accumulated by
// column-owner threads per chunk. Softmax over K=32 post-GEMM in registers
// (shfl.bfly across gid lanes). aw emitted as bf16x2 hi/lo pairs directly in
// k_agg's A-fragment layout [b][k][n/2]. Deterministic sum_aw partials.
// Block = (b, 512-n tile); 8 warps x 64 n; acc 16k x 16n x ... = 64 f32/thr.
// Grid 18 x 16 = 288 blocks, 2 CTAs/SM (80 KB smem).
// ---------------------------------------------------------------------------
__global__ void __launch_bounds__(256, 2) k_assign(
    const float* __restrict__ x, const float* __restrict__ cw,
    const float* __restrict__ scale)
{
    extern __shared__ float sm[];
    float*    xs  = sm;                               // [2][CC][XPA]
    unsigned* cwh = (unsigned*)(sm + 2 * CC * XPA);   // [2][32][CWP]
    unsigned* cwl = cwh + 2 * 32 * CWP;               // [2][32][CWP]
    float*    x2s = (float*)(cwl + 2 * 32 * CWP);     // [512]
    float*    s_scale = x2s + 512;                    // [32]
    float*    s_sc2   = s_scale + 32;                 // [32]
    float*    swred   = s_sc2 + 32;                   // [8][32]

    const int tid = threadIdx.x, w = tid >> 5, l = tid & 31;
    const int gid = l >> 2, tig = l & 3;
    const int b  = blockIdx.y;
    const int n0 = blockIdx.x * TN;

    // c2 & scale constants (threads 0..31; cw rows L2-hot after first wave)
    if (tid < 32) {
        const float4* cwr4 = (const float4*)(cw + tid * Cv);
        float s2 = 0.0f;
        #pragma unroll 8
        for (int j = 0; j < Cv / 4; j++) {
            float4 v = cwr4[j];
            s2 += v.x * v.x + v.y * v.y + v.z * v.z + v.w * v.w;
        }
        float sk = scale[tid];
        s_scale[tid] = sk;
        s_sc2[tid]   = sk * s2;
    }

    // x staging: thread covers row c = tid>>4, 32 floats at (tid&15)*32
    const int src_c = tid >> 4, src_r = tid & 15;
    const float* xsrc = x + (size_t)b * Cv * Nv + (size_t)src_c * Nv + n0 + src_r * 32;
    const unsigned xdst = smem_u32(xs) + (unsigned)(src_c * XPA + src_r * 32) * 4;

    // cw staging: thread loads float2 of row k = tid>>3 at c-pair (tid&7)*2
    const int cwk = tid >> 3, cwc = (tid & 7) * 2;
    const float* cwsrc = cw + (size_t)cwk * Cv + cwc;

    float acc[8][2][4];
    #pragma unroll
    for (int ct = 0; ct < 8; ct++)
        #pragma unroll
        for (int mt = 0; mt < 2; mt++)
            #pragma unroll
            for (int i = 0; i < 4; i++) acc[ct][mt][i] = 0.0f;
    u64 x2p = 0ull;                       // x2 for owned columns 2*tid, 2*tid+1

    // prologue: chunk 0
    #pragma unroll
    for (int j = 0; j < 8; j++) cp16(xdst + 16u * j, xsrc + 4 * j);
    CP_COMMIT();
    float2 cwr = *(const float2*)cwsrc;

    for (int t = 0; t < NCC; t++) {
        __syncthreads();                   // previous compute done; tile bufs free
        // split + store cw chunk t into tile buf t&1
        {
            unsigned h0 = tf32_of(cwr.x), h1 = tf32_of(cwr.y);
            unsigned l0 = tf32_of(cwr.x - __uint_as_float(h0));
            unsigned l1 = tf32_of(cwr.y - __uint_as_float(h1));
            int o = (t & 1) * 32 * CWP + cwk * CWP + cwc;
            cwh[o] = h0; cwh[o + 1] = h1;
            cwl[o] = l0; cwl[o + 1] = l1;
        }
        if (t + 1 < NCC) {
            const int c0n = (t + 1) * CC;
            #pragma unroll
            for (int j = 0; j < 8; j++)
                cp16(xdst + (unsigned)(((t + 1) & 1) * CC * XPA) * 4 + 16u * j,
                     xsrc + (size_t)c0n * Nv + 4 * j);
            CP_COMMIT();
            cwr = *(const float2*)(cwsrc + (t + 1) * CC);
            CP_WAIT(1);                    // x chunk t landed (t+1 in flight)
        } else {
            CP_WAIT(0);
        }
        __syncthreads();                   // cw tile + x chunk t visible

        const float* xt = xs + (t & 1) * CC * XPA;
        // x2 partial for owned columns
        #pragma unroll
        for (int c = 0; c < CC; c++) {
            float2 v = *(const float2*)(xt + c * XPA + 2 * tid);
            u64 vp = pack2(v.x, v.y);
            x2p = ffma2(vp, vp, x2p);
        }

        // MMA: 2 k8-steps over this chunk's 16 c
        const unsigned* ch = cwh + (t & 1) * 32 * CWP;
        const unsigned* cl = cwl + (t & 1) * 32 * CWP;
        #pragma unroll
        for (int s = 0; s < 2; s++) {
            unsigned ah[2][4], al[2][4];
            #pragma unroll
            for (int mt = 0; mt < 2; mt++) {
                int r0 = (mt * 16 + gid) * CWP + s * 8 + tig;
                int r1 = (mt * 16 + gid + 8) * CWP + s * 8 + tig;
                ah[mt][0] = ch[r0]; ah[mt][1] = ch[r1];
                ah[mt][2] = ch[r0 + 4]; ah[mt][3] = ch[r1 + 4];
                al[mt][0] = cl[r0]; al[mt][1] = cl[r1];
                al[mt][2] = cl[r0 + 4]; al[mt][3] = cl[r1 + 4];
            }
            const float* b0p = xt + (s * 8 + tig) * XPA + w * 64 + gid;
            const float* b1p = xt + (s * 8 + tig + 4) * XPA + w * 64 + gid;
            #pragma unroll
            for (int ct = 0; ct < 8; ct++) {
                float f0 = b0p[ct * 8], f1 = b1p[ct * 8];
                unsigned bh0 = tf32_of(f0), bh1 = tf32_of(f1);
                unsigned bl0 = tf32_of(f0 - __uint_as_float(bh0));
                unsigned bl1 = tf32_of(f1 - __uint_as_float(bh1));
                #pragma unroll
                for (int mt = 0; mt < 2; mt++) {
                    MMA8(acc[ct][mt], ah[mt][0], ah[mt][1], ah[mt][2], ah[mt][3], bh0, bh1);
                    MMA8(acc[ct][mt], al[mt][0], al[mt][1], al[mt][2], al[mt][3], bh0, bh1);
                    MMA8(acc[ct][mt], ah[mt][0], ah[mt][1], ah[mt][2], ah[mt][3], bl0, bl1);
                }
            }
        }
    }

    // publish x2
    __syncthreads();
    {
        float a, bb; unpack2(x2p, a, bb);
        x2s[2 * tid] = a; x2s[2 * tid + 1] = bb;
    }
    __syncthreads();

    // softmax over K=32 per n-column + aw store + sum_aw
    float scl[4], sc2[4];
    #pragma unroll
    for (int i = 0; i < 4; i++) { scl[i] = s_scale[gid + 8 * i]; sc2[i] = s_sc2[gid + 8 * i]; }
    float sumk[4] = {0.0f, 0.0f, 0.0f, 0.0f};
    const size_t awbase = (size_t)b * Kv * (Nv / 2) + ((n0 + w * 64) >> 1) + tig;

    #pragma unroll
    for (int ct = 0; ct < 8; ct++) {
        float x2a = x2s[w * 64 + ct * 8 + 2 * tig];
        float x2b = x2s[w * 64 + ct * 8 + 2 * tig + 1];
        float LA[4], LB[4];
        LA[0] = fmaf(scl[0], x2a - 2.0f * acc[ct][0][0], sc2[0]);
        LB[0] = fmaf(scl[0], x2b - 2.0f * acc[ct][0][1], sc2[0]);
        LA[1] = fmaf(scl[1], x2a - 2.0f * acc[ct][0][2], sc2[1]);
        LB[1] = fmaf(scl[1], x2b - 2.0f * acc[ct][0][3], sc2[1]);
        LA[2] = fmaf(scl[2], x2a - 2.0f * acc[ct][1][0], sc2[2]);
        LB[2] = fmaf(scl[2], x2b - 2.0f * acc[ct][1][1], sc2[2]);
        LA[3] = fmaf(scl[3], x2a - 2.0f * acc[ct][1][2], sc2[3]);
        LB[3] = fmaf(scl[3], x2b - 2.0f * acc[ct][1][3], sc2[3]);

        float ma = fmaxf(fmaxf(LA[0], LA[1]), fmaxf(LA[2], LA[3]));
        float mb = fmaxf(fmaxf(LB[0], LB[1]), fmaxf(LB[2], LB[3]));
        ma = fmaxf(ma, __shfl_xor_sync(0xffffffffu, ma, 4));
        ma = fmaxf(ma, __shfl_xor_sync(0xffffffffu, ma, 8));
        ma = fmaxf(ma, __shfl_xor_sync(0xffffffffu, ma, 16));
        mb = fmaxf(mb, __shfl_xor_sync(0xffffffffu, mb, 4));
        mb = fmaxf(mb, __shfl_xor_sync(0xffffffffu, mb, 8));
        mb = fmaxf(mb, __shfl_xor_sync(0xffffffffu, mb, 16));

        float ea[4], eb[4];
        float sa = 0.0f, sb = 0.0f;
        #pragma unroll
        for (int i = 0; i < 4; i++) {
            ea[i] = __expf(LA[i] - ma); sa += ea[i];
            eb[i] = __expf(LB[i] - mb); sb += eb[i];
        }
        sa += __shfl_xor_sync(0xffffffffu, sa, 4);
        sa += __shfl_xor_sync(0xffffffffu, sa, 8);
        sa += __shfl_xor_sync(0xffffffffu, sa, 16);
        sb += __shfl_xor_sync(0xffffffffu, sb, 4);
        sb += __shfl_xor_sync(0xffffffffu, sb, 8);
        sb += __shfl_xor_sync(0xffffffffu, sb, 16);
        float ra = 1.0f / sa, rb = 1.0f / sb;

        #pragma unroll
        for (int i = 0; i < 4; i++) {
            float awa = ea[i] * ra, awb = eb[i] * rb;
            unsigned h  = bf2(awb, awa);                    // lo half = even n
            unsigned lo = bf2(awb - bhi(h), awa - blo(h));
            size_t addr = awbase + (size_t)(gid + 8 * i) * (Nv / 2) + ct * 4;
            g_aw2h[addr] = h;
            g_aw2l[addr] = lo;
            sumk[i] += awa + awb;
        }
    }

    // deterministic sum_aw: quad-reduce, per-warp slots, fixed-order final
    #pragma unroll
    for (int i = 0; i < 4; i++) {
        sumk[i] += __shfl_xor_sync(0xffffffffu, sumk[i], 1);
        sumk[i] += __shfl_xor_sync(0xffffffffu, sumk[i], 2);
    }
    if (tig == 0) {
        #pragma unroll
        for (int i = 0; i < 4; i++) swred[w * 32 + gid + 8 * i] = sumk[i];
    }
    __syncthreads();
    if (tid < Kv) {
        float s = 0.0f;
        #pragma unroll
        for (int ww = 0; ww < 8; ww++) s += swred[ww * 32 + tid];
        g_sawp[(b * NT + blockIdx.x) * Kv + tid] = s;
    }
}

// ---------------------------------------------------------------------------
// Kernel 2 (unchanged from R15): bf16-split tensor-core aggregation.
// ---------------------------------------------------------------------------
__global__ void __launch_bounds__(256, 2) k_agg(
    const float* __restrict__ x, float* __restrict__ part)
{
    extern __shared__ float sm[];
    float*    raw = sm;                                  // [2][256][RP] fp32
    unsigned* xh  = (unsigned*)(sm + 2 * 256 * RP);      // [256][TP] bf16x2 hi
    unsigned* xl  = xh + 256 * TP;                       // [256][TP] bf16x2 lo
    unsigned* awh = xl + 256 * TP;                       // [2][32][TP]
    unsigned* awl = awh + 2 * 32 * TP;                   // [2][32][TP]
    const unsigned raw_u = smem_u32(raw);
    const unsigned awh_u = smem_u32(awh);
    const unsigned awl_u = smem_u32(awl);

    const int tid = threadIdx.x, w = tid >> 5, l = tid & 31;
    const int gid = l >> 2, tig = l & 3;
    const int b  = blockIdx.y;
    const int ch = blockIdx.x >> 3;
    const int sl = blockIdx.x & 7;
    const int mh = w & 1;                  // k-half
    const int cq = w >> 1;                 // c-quad (64 c)
    const int nst = sl * NSL;
    const int c0g = ch * CHC;

    const float* xb = x + (size_t)b * Cv * Nv + (size_t)(c0g + tid) * Nv + nst;
    const unsigned* ahs = g_aw2h + (size_t)b * Kv * (Nv / 2) + (nst >> 1);
    const unsigned* als = g_aw2l + (size_t)b * Kv * (Nv / 2) + (nst >> 1);

    float acc[8][4];
    #pragma unroll
    for (int ct = 0; ct < 8; ct++)
        #pragma unroll
        for (int i = 0; i < 4; i++) acc[ct][i] = 0.0f;

    const int awk = (tid & 63) >> 1, awhf = tid & 1;
    const unsigned awdst = ((tid < 64) ? awh_u : awl_u)
                         + (unsigned)(awk * TP + awhf * 4) * 4;
    const unsigned* awsrc = (tid < 64) ? ahs : als;

    #pragma unroll
    for (int j = 0; j < 4; j++)
        cp16(raw_u + (unsigned)(tid * RP + 4 * j) * 4, xb + 4 * j);
    if (tid < 128)
        cp16(awdst, awsrc + (size_t)awk * (Nv / 2) + awhf * 4);
    CP_COMMIT();

    for (int t = 0; t < NCH; t++) {
        __syncthreads();
        if (t + 1 < NCH) {
            const int sb = (t + 1) & 1;
            const int n0 = (t + 1) * CHN;
            #pragma unroll
            for (int j = 0; j < 4; j++)
                cp16(raw_u + (unsigned)(sb * 256 * RP + tid * RP + 4 * j) * 4,
                     xb + n0 + 4 * j);
            if (tid < 128)
                cp16(awdst + (unsigned)(sb * 32 * TP) * 4,
                     awsrc + (size_t)awk * (Nv / 2) + (t + 1) * (CHN / 2) + awhf * 4);
            CP_COMMIT();
            CP_WAIT(1);
        } else {
            CP_WAIT(0);
        }

        {
            const float* rr = raw + (t & 1) * 256 * RP + tid * RP;
            unsigned hrow[8], lrow[8];
            #pragma unroll
            for (int j = 0; j < 4; j++) {
                float4 v = reinterpret_cast<const float4*>(rr)[j];
                unsigned h0 = bf2(v.y, v.x);
                unsigned h1 = bf2(v.w, v.z);
                float r0 = v.x - blo(h0), r1 = v.y - bhi(h0);
                float r2 = v.z - blo(h1), r3 = v.w - bhi(h1);
                hrow[2 * j] = h0; hrow[2 * j + 1] = h1;
                lrow[2 * j] = bf2(r1, r0); lrow[2 * j + 1] = bf2(r3, r2);
            }
            uint4* hd = reinterpret_cast<uint4*>(xh + tid * TP);
            uint4* ld = reinterpret_cast<uint4*>(xl + tid * TP);
            hd[0] = make_uint4(hrow[0], hrow[1], hrow[2], hrow[3]);
            hd[1] = make_uint4(hrow[4], hrow[5], hrow[6], hrow[7]);
            ld[0] = make_uint4(lrow[0], lrow[1], lrow[2], lrow[3]);
            ld[1] = make_uint4(lrow[4], lrow[5], lrow[6], lrow[7]);
        }
        __syncthreads();

        const unsigned* aht = awh + (t & 1) * 32 * TP + (mh * 16 + gid) * TP;
        const unsigned* alt = awl + (t & 1) * 32 * TP + (mh * 16 + gid) * TP;
        unsigned Ah0 = aht[tig],          Ah1 = aht[8 * TP + tig];
        unsigned Ah2 = aht[tig + 4],      Ah3 = aht[8 * TP + tig + 4];
        unsigned Al0 = alt[tig],          Al1 = alt[8 * TP + tig];
        unsigned Al2 = alt[tig + 4],      Al3 = alt[8 * TP + tig + 4];

        unsigned bh0[8], bh1[8], bl0[8], bl1[8];
        #pragma unroll
        for (int ct = 0; ct < 8; ct++) {
            int cc = cq * 64 + ct * 8 + gid;
            bh0[ct] = xh[cc * TP + tig];
            bh1[ct] = xh[cc * TP + tig + 4];
            bl0[ct] = xl[cc * TP + tig];
            bl1[ct] = xl[cc * TP + tig + 4];
        }
        #pragma unroll
        for (int ct = 0; ct < 8; ct++)
            MMA16(acc[ct], Ah0, Ah1, Ah2, Ah3, bh0[ct], bh1[ct]);
        #pragma unroll
        for (int ct = 0; ct < 8; ct++)
            MMA16(acc[ct], Al0, Al1, Al2, Al3, bh0[ct], bh1[ct]);
        #pragma unroll
        for (int ct = 0; ct < 8; ct++)
            MMA16(acc[ct], Ah0, Ah1, Ah2, Ah3, bl0[ct], bl1[ct]);
    }

    float* pr0 = part + (((size_t)sl * Bv + b) * Kv + mh * 16 + gid) * Cv
                      + c0g + cq * 64;
    #pragma unroll
    for (int ct = 0; ct < 8; ct++) {
        int cc = ct * 8 + tig * 2;
        *reinterpret_cast<float2*>(pr0 + cc)          = make_float2(acc[ct][0], acc[ct][1]);
        *reinterpret_cast<float2*>(pr0 + 8 * Cv + cc) = make_float2(acc[ct][2], acc[ct][3]);
    }
}

// ---------------------------------------------------------------------------
// Kernel 3: out[b][k][c] = sum_s part[s][b][k][c] - sum_aw[b][k] * cw[k][c]
// ---------------------------------------------------------------------------
__global__ void __launch_bounds__(256) k_fin(
    const float* __restrict__ cw, float* __restrict__ out)
{
    __shared__ float ssum;
    const int bx = blockIdx.x;             // 0..511
    const int b = bx >> 5, k = bx & 31;
    const int tid = threadIdx.x;

    if (tid == 0) {
        float s = 0.0f;
        #pragma unroll
        for (int t = 0; t < NT; t++) s += g_sawp[(b * NT + t) * Kv + k];
        ssum = s;
    }
    __syncthreads();

    float2 v = make_float2(0.0f, 0.0f);
    #pragma unroll
    for (int s = 0; s < SL; s++) {
        float2 p = reinterpret_cast<const float2*>(
            g_part + (((size_t)s * Bv + b) * Kv + k) * Cv)[tid];
        v.x += p.x; v.y += p.y;
    }
    float2 cwv = reinterpret_cast<const float2*>(cw + (size_t)k * Cv)[tid];
    float sv = ssum;
    float2 o;
    o.x = v.x - sv * cwv.x;
    o.y = v.y - sv * cwv.y;
    reinterpret_cast<float2*>(out + ((size_t)b * Kv + k) * Cv)[tid] = o;
}

extern "C" void kernel_launch(void* const* d_in, const int* in_sizes, int n_in,
                              void* d_out, int out_size)
{
    const float* x  = (const float*)d_in[0];   // (B, C, H, W)
    const float* cw = (const float*)d_in[1];   // (K, C)
    const float* sc = (const float*)d_in[2];   // (K,)
    float* out = (float*)d_out;                // (B, K, C)

    const int asn_smem = (2 * CC * XPA + 4 * 32 * CWP + 512 + 64 + 256) * 4;   // 80128 B
    const int agg_smem = (2 * 256 * RP + 2 * 256 * TP + 4 * 32 * TP) * 4;      // 71680 B

    static int inited = 0;
    if (!inited) {
        cudaFuncSetAttribute(k_assign, cudaFuncAttributeMaxDynamicSharedMemorySize, asn_smem);
        cudaFuncSetAttribute(k_agg, cudaFuncAttributeMaxDynamicSharedMemorySize, agg_smem);
        inited = 1;
    }

    float* part;
    cudaGetSymbolAddress((void**)&part, g_part);   // no alloc; capture-safe

    k_assign<<<dim3(NT, Bv), 256, asn_smem>>>(x, cw, sc);
    k_agg<<<dim3(16, Bv), 256, agg_smem>>>(x, part);
    k_fin<<<Bv * Kv, 256>>>(cw, out);
}

// round 17
// speedup vs baseline: 1.1215x; 1.1215x over previous
#include <cuda_runtime.h>

#define Bv 16
#define Cv 512
#define Nv 9216
#define Kv 32
#define TN 512
#define NT (Nv / TN)      // 18 n-tiles for k_assign

#define SL 8              // k_agg n-slices per (b, c-half)
#define NSL (Nv / SL)     // 1152 n per slice
#define CHN 32            // k_agg n per staged chunk
#define NCH (NSL / CHN)   // 36 chunks
#define CHC 256           // k_agg c per block (c-half)
#define TP 20             // bf16x2 tile pitch (words): 16 pairs + pad

// scratch (no cudaMalloc allowed)
__device__ __align__(16) unsigned g_aw2h[(size_t)Bv * Kv * (Nv / 2)]; // 9.4 MB bf16x2 hi
__device__ __align__(16) unsigned g_aw2l[(size_t)Bv * Kv * (Nv / 2)]; // 9.4 MB bf16x2 lo
__device__ float g_sawp[Bv * NT * Kv];                                // per-tile sums of aw
__device__ __align__(16) float g_part[(size_t)SL * Bv * Kv * Cv];     // 8.4 MB partials

typedef unsigned long long u64;

__device__ __forceinline__ u64 pack2(float lo, float hi) {
    u64 r; asm("mov.b64 %0,{%1,%2};" : "=l"(r) : "f"(lo), "f"(hi)); return r;
}
__device__ __forceinline__ void unpack2(u64 v, float& lo, float& hi) {
    asm("mov.b64 {%0,%1},%2;" : "=f"(lo), "=f"(hi) : "l"(v));
}
__device__ __forceinline__ u64 ffma2(u64 a, u64 b, u64 c) {
    u64 d; asm("fma.rn.f32x2 %0,%1,%2,%3;" : "=l"(d) : "l"(a), "l"(b), "l"(c)); return d;
}
__device__ __forceinline__ unsigned smem_u32(const void* p) {
    unsigned r;
    asm("{ .reg .u64 t; cvta.to.shared.u64 t, %1; cvt.u32.u64 %0, t; }" : "=r"(r) : "l"(p));
    return r;
}
__device__ __forceinline__ void cp16(unsigned dst, const void* src) {
    asm volatile("cp.async.ca.shared.global [%0], [%1], 16;" :: "r"(dst), "l"(src));
}
#define CP_COMMIT() asm volatile("cp.async.commit_group;" ::: "memory")
#define CP_WAIT(N)  asm volatile("cp.async.wait_group %0;" :: "n"(N) : "memory")

// bf16x2 pack: result.lo = bf16(lo), result.hi = bf16(hi)
__device__ __forceinline__ unsigned bf2(float hi, float lo) {
    unsigned u; asm("cvt.rn.bf16x2.f32 %0, %1, %2;" : "=r"(u) : "f"(hi), "f"(lo)); return u;
}
__device__ __forceinline__ float blo(unsigned u) { return __uint_as_float(u << 16); }
__device__ __forceinline__ float bhi(unsigned u) { return __uint_as_float(u & 0xFFFF0000u); }

// m16n8k16 bf16 mma: D += A*B, fp32 accumulate
#define MMA16(d, a0, a1, a2, a3, b0, b1) \
    asm volatile("mma.sync.aligned.m16n8k16.row.col.f32.bf16.bf16.f32 " \
        "{%0,%1,%2,%3}, {%4,%5,%6,%7}, {%8,%9}, {%0,%1,%2,%3};" \
        : "+f"(d[0]), "+f"(d[1]), "+f"(d[2]), "+f"(d[3]) \
        : "r"(a0), "r"(a1), "r"(a2), "r"(a3), "r"(b0), "r"(b1))

// ---------------------------------------------------------------------------
// Kernel 1 (reverted to the measured-fast fp32 FFMA2 version, R15: 140.7 us):
// logits via scaled L2, softmax K=32, aw emitted as bf16x2 hi/lo in the
// k_agg A-fragment layout [b][k][n/2], deterministic per-tile sum_aw.
// ---------------------------------------------------------------------------
__global__ void __launch_bounds__(256, 2) k_assign(
    const float* __restrict__ x, const float* __restrict__ cw,
    const float* __restrict__ scale)
{
    extern __shared__ float cwT[];                 // [Cv][Kv] = 64 KB
    __shared__ float s_scale[Kv], s_sc2[Kv];
    const int tid = threadIdx.x;
    const int b   = blockIdx.y;
    const int n0  = blockIdx.x * TN;

    for (int i = tid; i < Cv * Kv; i += 256) {
        int k = i & 31, c = i >> 5;
        cwT[c * Kv + k] = cw[k * Cv + c];
    }
    __syncthreads();
    if (tid < Kv) {
        float s2 = 0.0f;
        #pragma unroll 8
        for (int c = 0; c < Cv; c++) { float v = cwT[c * Kv + tid]; s2 = fmaf(v, v, s2); }
        float sk = scale[tid];
        s_scale[tid] = sk;
        s_sc2[tid]   = sk * s2;
    }
    __syncthreads();

    const float* xb = x + (size_t)b * Cv * Nv + n0 + 2 * tid;

    u64 acc0[16], acc1[16];
    #pragma unroll
    for (int p = 0; p < 16; p++) { acc0[p] = 0ull; acc1[p] = 0ull; }
    u64 x2p = 0ull;

    float2 buf[8];
    #pragma unroll
    for (int i = 0; i < 8; i++) buf[i] = *reinterpret_cast<const float2*>(xb + (size_t)i * Nv);

    for (int c0 = 0; c0 < Cv; c0 += 8) {
        #pragma unroll
        for (int i = 0; i < 8; i++) {
            float2 xv = buf[i];
            int cn = c0 + 8 + i; cn = (cn < Cv) ? cn : 0;
            buf[i] = *reinterpret_cast<const float2*>(xb + (size_t)cn * Nv);

            u64 xp = pack2(xv.x, xv.y);
            x2p = ffma2(xp, xp, x2p);
            u64 d0 = pack2(xv.x, xv.x);
            u64 d1 = pack2(xv.y, xv.y);
            const ulonglong2* row = reinterpret_cast<const ulonglong2*>(cwT + (c0 + i) * Kv);
            #pragma unroll
            for (int q = 0; q < 8; q++) {
                ulonglong2 w = row[q];
                acc0[2 * q]     = ffma2(d0, w.x, acc0[2 * q]);
                acc1[2 * q]     = ffma2(d1, w.x, acc1[2 * q]);
                acc0[2 * q + 1] = ffma2(d0, w.y, acc0[2 * q + 1]);
                acc1[2 * q + 1] = ffma2(d1, w.y, acc1[2 * q + 1]);
            }
        }
    }

    float xcA[Kv], xcB[Kv], x2A, x2B;
    #pragma unroll
    for (int p = 0; p < 16; p++) {
        unpack2(acc0[p], xcA[2 * p], xcA[2 * p + 1]);
        unpack2(acc1[p], xcB[2 * p], xcB[2 * p + 1]);
    }
    unpack2(x2p, x2A, x2B);

    {
        float m = -1e30f;
        #pragma unroll
        for (int k = 0; k < Kv; k++) {
            float v = fmaf(s_scale[k], x2A - 2.0f * xcA[k], s_sc2[k]);
            xcA[k] = v; m = fmaxf(m, v);
        }
        float s = 0.0f;
        #pragma unroll
        for (int k = 0; k < Kv; k++) { float e = __expf(xcA[k] - m); xcA[k] = e; s += e; }
        float r = 1.0f / s;
        #pragma unroll
        for (int k = 0; k < Kv; k++) xcA[k] *= r;
    }
    {
        float m = -1e30f;
        #pragma unroll
        for (int k = 0; k < Kv; k++) {
            float v = fmaf(s_scale[k], x2B - 2.0f * xcB[k], s_sc2[k]);
            xcB[k] = v; m = fmaxf(m, v);
        }
        float s = 0.0f;
        #pragma unroll
        for (int k = 0; k < Kv; k++) { float e = __expf(xcB[k] - m); xcB[k] = e; s += e; }
        float r = 1.0f / s;
        #pragma unroll
        for (int k = 0; k < Kv; k++) xcB[k] *= r;
    }

    // aw as bf16x2 hi/lo, layout [b][k][n/2] (pair = (even n, odd n))
    {
        const size_t base = (size_t)b * Kv * (Nv / 2) + (n0 >> 1) + tid;
        #pragma unroll
        for (int k = 0; k < Kv; k++) {
            unsigned h = bf2(xcB[k], xcA[k]);          // lo half = even n
            float rA = xcA[k] - blo(h);
            float rB = xcB[k] - bhi(h);
            unsigned lo = bf2(rB, rA);
            g_aw2h[base + (size_t)k * (Nv / 2)] = h;
            g_aw2l[base + (size_t)k * (Nv / 2)] = lo;
        }
    }

    __syncthreads();
    float* red = cwT;                              // [256][33]
    #pragma unroll
    for (int k = 0; k < Kv; k++) red[tid * 33 + k] = xcA[k] + xcB[k];
    __syncthreads();
    if (tid < Kv) {
        float s = 0.0f;
        #pragma unroll 8
        for (int t = 0; t < 256; t++) s += red[t * 33 + tid];
        g_sawp[(b * NT + blockIdx.x) * Kv + tid] = s;
    }
}

// ---------------------------------------------------------------------------
// Kernel 2 (de-stalled bf16 tensor cores): partial[k][c] = sum_n aw[n][k]*
// x[c][n] for one (b, c-half 256, n-slice 1152). mma m16n8k16 bf16, 3 MMA
// passes (ah*bh + al*bh + ah*bl), fp32 acc.
// De-stall changes vs R15: CHN=32 (36 chunks), LDG.128 -> register convert ->
// STS bf16 tiles (no raw-fp32 smem hop, no x cp.async wait), ONE barrier per
// chunk (x double-buffered: STS t vs compute t-1 disjoint; aw TRIPLE-buffered
// so post-stage cp.async t+1 can't collide with laggards reading t-1).
// 95 KB smem, 2 CTAs/SM. Grid (2 ch x 8 sl) x 16 b = 256 blocks.
// ---------------------------------------------------------------------------
__global__ void __launch_bounds__(256, 2) k_agg(
    const float* __restrict__ x, float* __restrict__ part)
{
    extern __shared__ unsigned smu[];
    unsigned* xh  = smu;                     // [2][256][TP]
    unsigned* xl  = xh + 2 * 256 * TP;       // [2][256][TP]
    unsigned* awh = xl + 2 * 256 * TP;       // [3][32][TP]
    unsigned* awl = awh + 3 * 32 * TP;       // [3][32][TP]
    const unsigned awh_u = smem_u32(awh);
    const unsigned awl_u = smem_u32(awl);

    const int tid = threadIdx.x, w = tid >> 5, l = tid & 31;
    const int gid = l >> 2, tig = l & 3;
    const int b  = blockIdx.y;
    const int ch = blockIdx.x >> 3;
    const int sl = blockIdx.x & 7;
    const int mh = w & 1;                  // k-half
    const int cq = w >> 1;                 // c-quad (64 c)
    const int nst = sl * NSL;
    const int c0g = ch * CHC;

    const float* xb = x + (size_t)b * Cv * Nv + (size_t)(c0g + tid) * Nv + nst;
    const unsigned* ahs = g_aw2h + (size_t)b * Kv * (Nv / 2) + (nst >> 1);
    const unsigned* als = g_aw2l + (size_t)b * Kv * (Nv / 2) + (nst >> 1);

    float acc[8][4];
    #pragma unroll
    for (int ct = 0; ct < 8; ct++)
        #pragma unroll
        for (int i = 0; i < 4; i++) acc[ct][i] = 0.0f;

    // aw staging: tid<128 -> hi (row tid>>2, quad tid&3); else lo
    const int awk = (tid & 127) >> 2, awq = tid & 3;
    const unsigned awdst = ((tid < 128) ? awh_u : awl_u)
                         + (unsigned)(awk * TP + awq * 4) * 4;
    const unsigned* awsrc = (tid < 128) ? ahs : als;
    const size_t awoff = (size_t)awk * (Nv / 2) + awq * 4;

    // ---- prologue: LDG chunk 0 into regs; cp.async aw chunk 0 -> buf 0 ----
    float4 xr[8];
    #pragma unroll
    for (int j = 0; j < 8; j++)
        xr[j] = reinterpret_cast<const float4*>(xb)[j];
    cp16(awdst, awsrc + awoff);
    CP_COMMIT();

    for (int t = 0; t < NCH; t++) {
        // convert chunk t (in registers) -> STS bf16 tiles into x buf t&1
        {
            unsigned hrow[16], lrow[16];
            #pragma unroll
            for (int j = 0; j < 8; j++) {
                float4 v = xr[j];
                unsigned h0 = bf2(v.y, v.x);
                unsigned h1 = bf2(v.w, v.z);
                float r0 = v.x - blo(h0), r1 = v.y - bhi(h0);
                float r2 = v.z - blo(h1), r3 = v.w - bhi(h1);
                hrow[2 * j] = h0; hrow[2 * j + 1] = h1;
                lrow[2 * j] = bf2(r1, r0); lrow[2 * j + 1] = bf2(r3, r2);
            }
            uint4* hd = reinterpret_cast<uint4*>(xh + (t & 1) * 256 * TP + tid * TP);
            uint4* ld = reinterpret_cast<uint4*>(xl + (t & 1) * 256 * TP + tid * TP);
            #pragma unroll
            for (int q = 0; q < 4; q++) {
                hd[q] = make_uint4(hrow[4 * q], hrow[4 * q + 1], hrow[4 * q + 2], hrow[4 * q + 3]);
                ld[q] = make_uint4(lrow[4 * q], lrow[4 * q + 1], lrow[4 * q + 2], lrow[4 * q + 3]);
            }
        }
        // prefetch chunk t+1: LDG x into regs; cp.async aw -> buf (t+1)%3
        if (t + 1 < NCH) {
            const int n0 = (t + 1) * CHN;
            #pragma unroll
            for (int j = 0; j < 8; j++)
                xr[j] = *reinterpret_cast<const float4*>(xb + n0 + 4 * j);
            cp16(awdst + (unsigned)(((t + 1) % 3) * 32 * TP) * 4,
                 awsrc + awoff + (t + 1) * (CHN / 2));
            CP_COMMIT();
            CP_WAIT(1);                    // aw chunk t landed
        } else {
            CP_WAIT(0);
        }
        __syncthreads();                   // STS t + aw t visible; compute t-1 done

        // compute chunk t: 2 k16-steps
        const unsigned* xhs = xh + (t & 1) * 256 * TP + (cq * 64 + gid) * TP;
        const unsigned* xls = xl + (t & 1) * 256 * TP + (cq * 64 + gid) * TP;
        const unsigned* aht = awh + (t % 3) * 32 * TP + (mh * 16 + gid) * TP;
        const unsigned* alt = awl + (t % 3) * 32 * TP + (mh * 16 + gid) * TP;
        #pragma unroll
        for (int s = 0; s < 2; s++) {
            unsigned Ah0 = aht[s * 8 + tig],     Ah1 = aht[8 * TP + s * 8 + tig];
            unsigned Ah2 = aht[s * 8 + tig + 4], Ah3 = aht[8 * TP + s * 8 + tig + 4];
            unsigned Al0 = alt[s * 8 + tig],     Al1 = alt[8 * TP + s * 8 + tig];
            unsigned Al2 = alt[s * 8 + tig + 4], Al3 = alt[8 * TP + s * 8 + tig + 4];

            unsigned bh0[8], bh1[8], bl0[8], bl1[8];
            #pragma unroll
            for (int ct = 0; ct < 8; ct++) {
                const unsigned* xr0 = xhs + ct * 8 * TP + s * 8;
                const unsigned* xr1 = xls + ct * 8 * TP + s * 8;
                bh0[ct] = xr0[tig]; bh1[ct] = xr0[tig + 4];
                bl0[ct] = xr1[tig]; bl1[ct] = xr1[tig + 4];
            }
            #pragma unroll
            for (int ct = 0; ct < 8; ct++)
                MMA16(acc[ct], Ah0, Ah1, Ah2, Ah3, bh0[ct], bh1[ct]);
            #pragma unroll
            for (int ct = 0; ct < 8; ct++)
                MMA16(acc[ct], Al0, Al1, Al2, Al3, bh0[ct], bh1[ct]);
            #pragma unroll
            for (int ct = 0; ct < 8; ct++)
                MMA16(acc[ct], Ah0, Ah1, Ah2, Ah3, bl0[ct], bl1[ct]);
        }
    }

    // epilogue: warp writes its 16k x 64c partial tile
    float* pr0 = part + (((size_t)sl * Bv + b) * Kv + mh * 16 + gid) * Cv
                      + c0g + cq * 64;
    #pragma unroll
    for (int ct = 0; ct < 8; ct++) {
        int cc = ct * 8 + tig * 2;
        *reinterpret_cast<float2*>(pr0 + cc)          = make_float2(acc[ct][0], acc[ct][1]);
        *reinterpret_cast<float2*>(pr0 + 8 * Cv + cc) = make_float2(acc[ct][2], acc[ct][3]);
    }
}

// ---------------------------------------------------------------------------
// Kernel 3: out[b][k][c] = sum_s part[s][b][k][c] - sum_aw[b][k] * cw[k][c]
// ---------------------------------------------------------------------------
__global__ void __launch_bounds__(256) k_fin(
    const float* __restrict__ cw, float* __restrict__ out)
{
    __shared__ float ssum;
    const int bx = blockIdx.x;             // 0..511
    const int b = bx >> 5, k = bx & 31;
    const int tid = threadIdx.x;

    if (tid == 0) {
        float s = 0.0f;
        #pragma unroll
        for (int t = 0; t < NT; t++) s += g_sawp[(b * NT + t) * Kv + k];
        ssum = s;
    }
    __syncthreads();

    float2 v = make_float2(0.0f, 0.0f);
    #pragma unroll
    for (int s = 0; s < SL; s++) {
        float2 p = reinterpret_cast<const float2*>(
            g_part + (((size_t)s * Bv + b) * Kv + k) * Cv)[tid];
        v.x += p.x; v.y += p.y;
    }
    float2 cwv = reinterpret_cast<const float2*>(cw + (size_t)k * Cv)[tid];
    float sv = ssum;
    float2 o;
    o.x = v.x - sv * cwv.x;
    o.y = v.y - sv * cwv.y;
    reinterpret_cast<float2*>(out + ((size_t)b * Kv + k) * Cv)[tid] = o;
}

extern "C" void kernel_launch(void* const* d_in, const int* in_sizes, int n_in,
                              void* d_out, int out_size)
{
    const float* x  = (const float*)d_in[0];   // (B, C, H, W)
    const float* cw = (const float*)d_in[1];   // (K, C)
    const float* sc = (const float*)d_in[2];   // (K,)
    float* out = (float*)d_out;                // (B, K, C)

    const int asn_smem = Cv * Kv * 4;                                   // 65536 B
    const int agg_smem = (4 * 256 * TP + 6 * 32 * TP) * 4;              // 97280 B

    static int inited = 0;
    if (!inited) {
        cudaFuncSetAttribute(k_assign, cudaFuncAttributeMaxDynamicSharedMemorySize, asn_smem);
        cudaFuncSetAttribute(k_agg, cudaFuncAttributeMaxDynamicSharedMemorySize, agg_smem);
        inited = 1;
    }

    float* part;
    cudaGetSymbolAddress((void**)&part, g_part);   // no alloc; capture-safe

    k_assign<<<dim3(NT, Bv), 256, asn_smem>>>(x, cw, sc);
    k_agg<<<dim3(16, Bv), 256, agg_smem>>>(x, part);
    k_fin<<<Bv * Kv, 256>>>(cw, out);
}